// round 8
// baseline (speedup 1.0000x reference)
#include <cuda_runtime.h>
#include <mma.h>
using namespace nvcuda;

// Problem constants
#define BATCH   4
#define SEQLEN  65536
#define RC      32
#define OC      256
#define NBLOCKS 2
#define NLAYERS 10

#define TL      128           // positions per CTA in k_layer_tc
#define FGLD    132           // staging row stride
#define WALD    40            // weight A row stride
// fixed smem (floats): lo[40][FGLD] + fg[64][FGLD] + wA[3][64][WALD] + wAb1[64][8]
#define SM_FIXED (40 * FGLD + 64 * FGLD + 3 * 64 * WALD + 64 * 8)

#define HC      64            // head positions per CTA
#define HLDH    68            // head row stride

// -------- scratch (device globals; no allocation allowed) --------
__device__ float g_resid[2][BATCH * RC * SEQLEN];
__device__ float g_skip[BATCH * RC * SEQLEN];
__device__ float g_w1e[OC * 40];      // [256][40]: tf32(w1) | tf32(b1) | 0
__device__ float g_w2e[OC * 264];     // [256][264]: tf32(w2) | tf32(b2) | 0

// ----------------------------------------------------------------
// Prep: bias-extended head weights, pre-rounded to tf32.
// ----------------------------------------------------------------
__global__ void k_prepw(const float* __restrict__ w1, const float* __restrict__ b1,
                        const float* __restrict__ w2, const float* __restrict__ b2)
{
    int idx = blockIdx.x * blockDim.x + threadIdx.x;
    const int N2 = OC * 264;
    if (idx < N2) {
        int m = idx / 264, c = idx % 264;
        float v = (c < 256) ? w2[(size_t)m * 256 + c] : (c == 256 ? b2[m] : 0.f);
        g_w2e[idx] = wmma::__float_to_tf32(v);
    } else if (idx < N2 + OC * 40) {
        int j = idx - N2;
        int m = j / 40, c = j % 40;
        float v = (c < 32) ? w1[(size_t)m * 32 + c] : (c == 32 ? b1[m] : 0.f);
        g_w1e[j] = wmma::__float_to_tf32(v);
    }
}

// ----------------------------------------------------------------
// Kernel: gated dilated layer, TF32 wmma, register-fused gating.
// GEMM1: 9 k-steps (tapA 4 + tapB 4 + bias 1); f,g stay in fragments,
// lo = tf32(f*g) stored from fragments. GEMM2: 5 k-steps (w 4 + bias 1).
// Biases ride a ones-chunk in lo rows 32-39 (shared by both GEMMs).
// Layer 0 fuses the start conv into the halo load (x has 1 channel).
// ----------------------------------------------------------------
__global__ __launch_bounds__(256, 2)
void k_layer_tc(int ping,
                const float* __restrict__ fw, const float* __restrict__ fb,
                const float* __restrict__ gw, const float* __restrict__ gb,
                const float* __restrict__ rw, const float* __restrict__ rb,
                const float* __restrict__ sw, const float* __restrict__ sb,
                const float* __restrict__ x,
                const float* __restrict__ wst, const float* __restrict__ bst,
                int offA, int offB, int PAD, int HS, int firstLayer)
{
    extern __shared__ float smem[];
    float* halo = smem;                 // [32][HS], col PAD+n <-> global l0+n
    float* lo   = smem + 32 * HS;       // [40][FGLD]; rows 32-39 = ones chunk
    float* fg   = lo + 40 * FGLD;       // [64][FGLD], GEMM2 output staging
    float* wA   = fg + 64 * FGLD;       // [3][64][WALD] (tap0|tap1|res/skip+bias)
    float* wAb1 = wA + 3 * 64 * WALD;   // [64][8], GEMM1 bias A-tile

    int tid = threadIdx.x;
    int b = blockIdx.y;
    int l0 = blockIdx.x * TL;

    const float* __restrict__ rin = &g_resid[ping][(size_t)b * RC * SEQLEN];
    float* __restrict__ rout = &g_resid[ping ^ 1][(size_t)b * RC * SEQLEN];
    float* __restrict__ sk = &g_skip[(size_t)b * RC * SEQLEN];

    // --- tap + res/skip weights (cols 0-31), pre-rounded to tf32
    const float2* fw2 = (const float2*)fw;
    const float2* gw2 = (const float2*)gw;
    for (int i = tid; i < 64 * 32; i += 256) {
        int row = i >> 5, ci = i & 31;
        int c = row & 31;
        float t0, t1, t2;
        if (row < 32) {
            float2 t = fw2[c * 32 + ci];
            t0 = t.x; t1 = t.y; t2 = rw[c * 32 + ci];
        } else {
            float2 t = gw2[c * 32 + ci];
            t0 = t.x; t1 = t.y; t2 = sw[c * 32 + ci];
        }
        wA[0 * 64 * WALD + row * WALD + ci] = wmma::__float_to_tf32(t0);
        wA[1 * 64 * WALD + row * WALD + ci] = wmma::__float_to_tf32(t1);
        wA[2 * 64 * WALD + row * WALD + ci] = wmma::__float_to_tf32(t2);
    }
    // --- bias extensions: wA2 cols 32-39 (col32 = res/skip bias), wAb1 col0 = f/g bias
    for (int i = tid; i < 64 * 8; i += 256) {
        int row = i >> 3, col = i & 7;
        int c = row & 31;
        float v2 = (col == 0) ? ((row < 32) ? rb[c] : sb[c]) : 0.f;
        wA[2 * 64 * WALD + row * WALD + 32 + col] = wmma::__float_to_tf32(v2);
        float v1 = (col == 0) ? ((row < 32) ? fb[c] : gb[c]) : 0.f;
        wAb1[row * 8 + col] = wmma::__float_to_tf32(v1);
    }
    // --- ones chunk: lo rows 32-39 (row 32 = 1, rest 0), cols 0-127
    for (int i = tid; i < 8 * 128; i += 256) {
        int row = 32 + (i >> 7), col = i & 127;
        lo[row * FGLD + col] = (row == 32) ? 1.f : 0.f;
    }
    // --- residual halo load (zero-padded OOB); PAD and l0 multiples of 4
    {
        int c0 = (PAD + offA) & ~3;
        int c1 = (PAD + TL + offB + 4) & ~3;
        int w4 = (c1 - c0) >> 2;
        if (firstLayer) {
            const float* __restrict__ xb = &x[(size_t)b * SEQLEN];
            for (int i = tid; i < 32 * w4; i += 256) {
                int row = i / w4;
                int col = c0 + ((i - row * w4) << 2);
                int l = l0 - PAD + col;
                float4 v = make_float4(0.f, 0.f, 0.f, 0.f);
                if (l >= 0 && l < SEQLEN) {
                    float4 xv = *(const float4*)&xb[l];
                    float wv = wst[row], bv = bst[row];
                    v = make_float4(wv * xv.x + bv, wv * xv.y + bv,
                                    wv * xv.z + bv, wv * xv.w + bv);
                }
                *(float4*)&halo[row * HS + col] = v;
            }
        } else {
            for (int i = tid; i < 32 * w4; i += 256) {
                int row = i / w4;
                int col = c0 + ((i - row * w4) << 2);
                int l = l0 - PAD + col;
                float4 v = make_float4(0.f, 0.f, 0.f, 0.f);
                if (l >= 0 && l < SEQLEN)
                    v = *(const float4*)&rin[(size_t)row * SEQLEN + l];
                *(float4*)&halo[row * HS + col] = v;
            }
        }
    }
    __syncthreads();

    int warp = tid >> 5;
    int lane = tid & 31;
    int n0 = warp * 16;
    int lcol = n0 + (lane & 15);
    int cbase = (lane >> 4) * 16;

    // ---------------- GEMM1: [f;g] = Wfg @ [shifted resid] + bias ----------------
    wmma::fragment<wmma::accumulator, 16, 16, 8, float> acc[4];
#pragma unroll
    for (int mi = 0; mi < 4; mi++) wmma::fill_fragment(acc[mi], 0.f);

#pragma unroll
    for (int tap = 0; tap < 2; tap++) {
        const float* wAt = wA + tap * 64 * WALD;
        int tapOff = PAD + (tap ? offB : offA) + n0;
#pragma unroll
        for (int kf = 0; kf < 4; kf++) {
            wmma::fragment<wmma::matrix_a, 16, 16, 8, wmma::precision::tf32, wmma::row_major> a;
            wmma::fragment<wmma::matrix_b, 16, 16, 8, wmma::precision::tf32, wmma::row_major> bf;
            wmma::load_matrix_sync(bf, &halo[(kf * 8) * HS + tapOff], HS);
#pragma unroll
            for (int t = 0; t < bf.num_elements; t++)
                bf.x[t] = wmma::__float_to_tf32(bf.x[t]);
#pragma unroll
            for (int mi = 0; mi < 4; mi++) {
                wmma::load_matrix_sync(a, &wAt[(mi * 16) * WALD + kf * 8], WALD);
                wmma::mma_sync(acc[mi], a, bf, acc[mi]);
            }
        }
    }
    { // bias k-step: B = ones chunk (lo rows 32-39)
        wmma::fragment<wmma::matrix_b, 16, 16, 8, wmma::precision::tf32, wmma::row_major> bf;
        wmma::load_matrix_sync(bf, &lo[32 * FGLD + n0], FGLD);
#pragma unroll
        for (int mi = 0; mi < 4; mi++) {
            wmma::fragment<wmma::matrix_a, 16, 16, 8, wmma::precision::tf32, wmma::row_major> a;
            wmma::load_matrix_sync(a, &wAb1[(mi * 16) * 8], 8);
            wmma::mma_sync(acc[mi], a, bf, acc[mi]);
        }
    }

    // ---------------- lo = tf32(f * g) on fragments (identical layouts) ----------------
#pragma unroll
    for (int mi = 0; mi < 2; mi++) {
#pragma unroll
        for (int t = 0; t < acc[mi].num_elements; t++)
            acc[mi].x[t] = wmma::__float_to_tf32(acc[mi].x[t] * acc[mi + 2].x[t]);
        wmma::store_matrix_sync(&lo[(mi * 16) * FGLD + n0], acc[mi], FGLD, wmma::mem_row_major);
    }
    __syncwarp();

    // ---------------- GEMM2: [res;skip] = Wrs @ [lo] + bias (5 k-steps) ----------------
#pragma unroll
    for (int mi = 0; mi < 4; mi++) wmma::fill_fragment(acc[mi], 0.f);
    {
        const float* wA2 = wA + 2 * 64 * WALD;
#pragma unroll
        for (int kf = 0; kf < 5; kf++) {
            wmma::fragment<wmma::matrix_b, 16, 16, 8, wmma::precision::tf32, wmma::row_major> bf;
            wmma::load_matrix_sync(bf, &lo[(kf * 8) * FGLD + n0], FGLD);
#pragma unroll
            for (int mi = 0; mi < 4; mi++) {
                wmma::fragment<wmma::matrix_a, 16, 16, 8, wmma::precision::tf32, wmma::row_major> a;
                wmma::load_matrix_sync(a, &wA2[(mi * 16) * WALD + kf * 8], WALD);
                wmma::mma_sync(acc[mi], a, bf, acc[mi]);
            }
        }
    }
#pragma unroll
    for (int mi = 0; mi < 4; mi++)
        wmma::store_matrix_sync(&fg[(mi * 16) * FGLD + n0], acc[mi], FGLD, wmma::mem_row_major);
    __syncwarp();

    // ---------------- residual + skip epilogue (biases folded) ----------------
#pragma unroll
    for (int cc = 0; cc < 16; cc++) {
        int c = cbase + cc;
        size_t gidx = (size_t)c * SEQLEN + l0 + lcol;
        float rv = halo[c * HS + PAD + lcol] + fg[c * FGLD + lcol];
        float sv = fg[(32 + c) * FGLD + lcol];
        if (!firstLayer) sv += sk[gidx];
        rout[gidx] = rv;
        sk[gidx] = sv;
    }
}

// ----------------------------------------------------------------
// Fused head: hid = relu(W1e @ [relu(skip);1]); out = W2e @ [hid;1].
// CTA = 64 positions (smem ~83KB -> 2 CTAs/SM); 8 warps x 32 out rows.
// All smem operands pre-rounded tf32 -> no conversions in mainloops.
// ----------------------------------------------------------------
__global__ __launch_bounds__(256, 2)
void k_head(float* __restrict__ out)
{
    extern __shared__ float smem[];
    float* hid = smem;                  // [264][HLDH]
    float* bsk = smem + 264 * HLDH;     // [40][HLDH]

    int tid = threadIdx.x;
    int b = blockIdx.y;
    int l0 = blockIdx.x * HC;

    // B tile: tf32(relu(skip)) rows 0-31, row 32 = 1, rows 33-39 = 0
    for (int i = tid; i < 32 * 16; i += 256) {
        int row = i >> 4, n4 = (i & 15) << 2;
        float4 v = *(const float4*)&g_skip[((size_t)b * RC + row) * SEQLEN + l0 + n4];
        v.x = wmma::__float_to_tf32(v.x > 0.f ? v.x : 0.f);
        v.y = wmma::__float_to_tf32(v.y > 0.f ? v.y : 0.f);
        v.z = wmma::__float_to_tf32(v.z > 0.f ? v.z : 0.f);
        v.w = wmma::__float_to_tf32(v.w > 0.f ? v.w : 0.f);
        *(float4*)&bsk[row * HLDH + n4] = v;
    }
    for (int i = tid; i < 8 * HC; i += 256) {
        int row = 32 + (i >> 6), col = i & 63;
        bsk[row * HLDH + col] = (row == 32) ? 1.f : 0.f;
    }
    for (int i = tid; i < 8 * HC; i += 256) {
        int row = 256 + (i >> 6), col = i & 63;
        hid[row * HLDH + col] = (row == 256) ? 1.f : 0.f;
    }
    __syncthreads();

    int warp = tid >> 5;
    wmma::fragment<wmma::accumulator, 16, 16, 8, float> acc[2][4];

    // ---------------- GEMM1 ----------------
#pragma unroll
    for (int mi = 0; mi < 2; mi++)
#pragma unroll
        for (int ni = 0; ni < 4; ni++) wmma::fill_fragment(acc[mi][ni], 0.f);

#pragma unroll
    for (int kf = 0; kf < 5; kf++) {
        wmma::fragment<wmma::matrix_b, 16, 16, 8, wmma::precision::tf32, wmma::row_major> bf[4];
#pragma unroll
        for (int ni = 0; ni < 4; ni++)
            wmma::load_matrix_sync(bf[ni], &bsk[(kf * 8) * HLDH + ni * 16], HLDH);
#pragma unroll
        for (int mi = 0; mi < 2; mi++) {
            wmma::fragment<wmma::matrix_a, 16, 16, 8, wmma::precision::tf32, wmma::row_major> a;
            wmma::load_matrix_sync(a, &g_w1e[(warp * 32 + mi * 16) * 40 + kf * 8], 40);
#pragma unroll
            for (int ni = 0; ni < 4; ni++)
                wmma::mma_sync(acc[mi][ni], a, bf[ni], acc[mi][ni]);
        }
    }
#pragma unroll
    for (int mi = 0; mi < 2; mi++)
#pragma unroll
        for (int ni = 0; ni < 4; ni++) {
#pragma unroll
            for (int t = 0; t < acc[mi][ni].num_elements; t++) {
                float v = acc[mi][ni].x[t];
                acc[mi][ni].x[t] = wmma::__float_to_tf32(v > 0.f ? v : 0.f);
            }
            wmma::store_matrix_sync(&hid[(warp * 32 + mi * 16) * HLDH + ni * 16],
                                    acc[mi][ni], HLDH, wmma::mem_row_major);
        }
    __syncthreads();

    // ---------------- GEMM2: K = 264 ----------------
#pragma unroll
    for (int mi = 0; mi < 2; mi++)
#pragma unroll
        for (int ni = 0; ni < 4; ni++) wmma::fill_fragment(acc[mi][ni], 0.f);

    for (int kf = 0; kf < 33; kf++) {
        wmma::fragment<wmma::matrix_b, 16, 16, 8, wmma::precision::tf32, wmma::row_major> bf[4];
#pragma unroll
        for (int ni = 0; ni < 4; ni++)
            wmma::load_matrix_sync(bf[ni], &hid[(kf * 8) * HLDH + ni * 16], HLDH);
#pragma unroll
        for (int mi = 0; mi < 2; mi++) {
            wmma::fragment<wmma::matrix_a, 16, 16, 8, wmma::precision::tf32, wmma::row_major> a;
            wmma::load_matrix_sync(a, &g_w2e[(warp * 32 + mi * 16) * 264 + kf * 8], 264);
#pragma unroll
            for (int ni = 0; ni < 4; ni++)
                wmma::mma_sync(acc[mi][ni], a, bf[ni], acc[mi][ni]);
        }
    }
#pragma unroll
    for (int mi = 0; mi < 2; mi++)
#pragma unroll
        for (int ni = 0; ni < 4; ni++) {
            float* dst = &out[((size_t)b * OC + warp * 32 + mi * 16) * SEQLEN
                              + l0 + ni * 16];
            wmma::store_matrix_sync(dst, acc[mi][ni], SEQLEN, wmma::mem_row_major);
        }
}

// ----------------------------------------------------------------
extern "C" void kernel_launch(void* const* d_in, const int* in_sizes, int n_in,
                              void* d_out, int out_size)
{
    const float* x       = (const float*)d_in[0];
    const float* w_start = (const float*)d_in[1];
    const float* b_start = (const float*)d_in[2];
    const float* filt_w  = (const float*)d_in[3];
    const float* filt_b  = (const float*)d_in[4];
    const float* gate_w  = (const float*)d_in[5];
    const float* gate_b  = (const float*)d_in[6];
    const float* res_w   = (const float*)d_in[7];
    const float* res_b   = (const float*)d_in[8];
    const float* skip_w  = (const float*)d_in[9];
    const float* skip_b  = (const float*)d_in[10];
    const float* w_end1  = (const float*)d_in[11];
    const float* b_end1  = (const float*)d_in[12];
    const float* w_end2  = (const float*)d_in[13];
    const float* b_end2  = (const float*)d_in[14];
    float* out = (float*)d_out;

    static int smem_set = 0;
    if (!smem_set) {
        int hsMax = (TL + 2 * 256 + 11) & ~3;
        cudaFuncSetAttribute(k_layer_tc, cudaFuncAttributeMaxDynamicSharedMemorySize,
                             (SM_FIXED + 32 * hsMax) * (int)sizeof(float));
        cudaFuncSetAttribute(k_head, cudaFuncAttributeMaxDynamicSharedMemorySize,
                             (264 * HLDH + 40 * HLDH) * (int)sizeof(float));
        smem_set = 1;
    }

    {
        int n = OC * 264 + OC * 40;
        k_prepw<<<(n + 255) / 256, 256>>>(w_end1, b_end1, w_end2, b_end2);
    }

    int ping = 0;
    dim3 gl(SEQLEN / TL, BATCH);
    for (int blk = 0; blk < NBLOCKS; blk++) {
        for (int i = 0; i < NLAYERS; i++) {
            int li = blk * NLAYERS + i;
            int offA, offB;
            if (i == 0) { offA = -1; offB = 0; }
            else { int h = 1 << (i - 1); offA = -h; offB = h; }
            int CO = -offA > offB ? -offA : offB;
            int PAD = (CO + 3) & ~3;
            int HS = (TL + 2 * PAD + 11) & ~3;
            int smemBytes = (SM_FIXED + 32 * HS) * (int)sizeof(float);
            k_layer_tc<<<gl, 256, smemBytes>>>(ping,
                filt_w + (size_t)li * RC * RC * 2, filt_b + (size_t)li * RC,
                gate_w + (size_t)li * RC * RC * 2, gate_b + (size_t)li * RC,
                res_w  + (size_t)li * RC * RC,     res_b  + (size_t)li * RC,
                skip_w + (size_t)li * RC * RC,     skip_b + (size_t)li * RC,
                x, w_start, b_start,
                offA, offB, PAD, HS, (li == 0) ? 1 : 0);
            ping ^= 1;
        }
    }

    dim3 gh(SEQLEN / HC, BATCH);
    k_head<<<gh, 256, (264 * HLDH + 40 * HLDH) * sizeof(float)>>>(out);
}

// round 9
// speedup vs baseline: 1.0654x; 1.0654x over previous
#include <cuda_runtime.h>
#include <mma.h>
using namespace nvcuda;

// Problem constants
#define BATCH   4
#define SEQLEN  65536
#define RC      32
#define OC      256
#define NBLOCKS 2
#define NLAYERS 10

#define TL      128           // positions per CTA in k_layer_tc
#define FGLD    132           // merged staging row stride (odd mult of 4)
#define WALD    40            // weight A row stride
// fixed smem (floats): u[64][FGLD] + wA[3][64][WALD] + bias[128]
#define SM_FIXED (64 * FGLD + 3 * 64 * WALD + 128)

#define HC      128           // head positions per CTA
#define HLDH    132           // head row stride

// -------- scratch (device globals; no allocation allowed) --------
__device__ float g_resid[2][BATCH * RC * SEQLEN];
__device__ float g_skip[BATCH * RC * SEQLEN];
__device__ float g_w1e[OC * 40];      // [256][40]: tf32(w1) | tf32(b1) | 0
__device__ float g_w2e[OC * 264];     // [256][264]: tf32(w2) | tf32(b2) | 0

// ----------------------------------------------------------------
// Prep: bias-extended head weights, pre-rounded to tf32.
// ----------------------------------------------------------------
__global__ void k_prepw(const float* __restrict__ w1, const float* __restrict__ b1,
                        const float* __restrict__ w2, const float* __restrict__ b2)
{
    int idx = blockIdx.x * blockDim.x + threadIdx.x;
    const int N2 = OC * 264;
    if (idx < N2) {
        int m = idx / 264, c = idx % 264;
        float v = (c < 256) ? w2[(size_t)m * 256 + c] : (c == 256 ? b2[m] : 0.f);
        g_w2e[idx] = wmma::__float_to_tf32(v);
    } else if (idx < N2 + OC * 40) {
        int j = idx - N2;
        int m = j / 40, c = j % 40;
        float v = (c < 32) ? w1[(size_t)m * 32 + c] : (c == 32 ? b1[m] : 0.f);
        g_w1e[j] = wmma::__float_to_tf32(v);
    }
}

// ----------------------------------------------------------------
// Gated dilated layer (R7 structure, merged staging buffer).
// u[64][FGLD] serves as fg (GEMM1 out), lo (rows 0-31), and GEMM2 out:
// all accesses to a given column slice are by the owning warp, and wmma
// _sync ops are warp-synchronizing, so aliasing is hazard-free.
// Layer 0 fuses the start conv into the halo load.
// ----------------------------------------------------------------
__global__ __launch_bounds__(256, 2)
void k_layer_tc(int ping,
                const float* __restrict__ fw, const float* __restrict__ fb,
                const float* __restrict__ gw, const float* __restrict__ gb,
                const float* __restrict__ rw, const float* __restrict__ rb,
                const float* __restrict__ sw, const float* __restrict__ sb,
                const float* __restrict__ x,
                const float* __restrict__ wst, const float* __restrict__ bst,
                int offA, int offB, int PAD, int HS, int firstLayer)
{
    extern __shared__ float smem[];
    float* halo = smem;                 // [32][HS], col PAD+n <-> global l0+n
    float* u    = smem + 32 * HS;       // [64][FGLD] merged staging
    float* wA   = u + 64 * FGLD;        // [3][64][WALD], tf32-rounded
    float* bias = wA + 3 * 64 * WALD;   // [128]

    int tid = threadIdx.x;
    int b = blockIdx.y;
    int l0 = blockIdx.x * TL;

    const float* __restrict__ rin = &g_resid[ping][(size_t)b * RC * SEQLEN];
    float* __restrict__ rout = &g_resid[ping ^ 1][(size_t)b * RC * SEQLEN];
    float* __restrict__ sk = &g_skip[(size_t)b * RC * SEQLEN];

    // --- weights -> A form, pre-rounded to tf32
    const float2* fw2 = (const float2*)fw;
    const float2* gw2 = (const float2*)gw;
    for (int i = tid; i < 64 * 32; i += 256) {
        int row = i >> 5, ci = i & 31;
        int c = row & 31;
        float t0, t1, t2;
        if (row < 32) {
            float2 t = fw2[c * 32 + ci];
            t0 = t.x; t1 = t.y; t2 = rw[c * 32 + ci];
        } else {
            float2 t = gw2[c * 32 + ci];
            t0 = t.x; t1 = t.y; t2 = sw[c * 32 + ci];
        }
        wA[0 * 64 * WALD + row * WALD + ci] = wmma::__float_to_tf32(t0);
        wA[1 * 64 * WALD + row * WALD + ci] = wmma::__float_to_tf32(t1);
        wA[2 * 64 * WALD + row * WALD + ci] = wmma::__float_to_tf32(t2);
    }
    if (tid < 32) {
        bias[tid]      = fb[tid];
        bias[32 + tid] = gb[tid];
        bias[64 + tid] = rb[tid];
        bias[96 + tid] = sb[tid];
    }

    // --- residual halo load (zero-padded OOB); PAD and l0 multiples of 4
    {
        int c0 = (PAD + offA) & ~3;
        int c1 = (PAD + TL + offB + 4) & ~3;
        int w4 = (c1 - c0) >> 2;
        if (firstLayer) {
            const float* __restrict__ xb = &x[(size_t)b * SEQLEN];
            for (int i = tid; i < 32 * w4; i += 256) {
                int row = i / w4;
                int col = c0 + ((i - row * w4) << 2);
                int l = l0 - PAD + col;
                float4 v = make_float4(0.f, 0.f, 0.f, 0.f);
                if (l >= 0 && l < SEQLEN) {
                    float4 xv = *(const float4*)&xb[l];
                    float wv = wst[row], bv = bst[row];
                    v = make_float4(wv * xv.x + bv, wv * xv.y + bv,
                                    wv * xv.z + bv, wv * xv.w + bv);
                }
                *(float4*)&halo[row * HS + col] = v;
            }
        } else {
            for (int i = tid; i < 32 * w4; i += 256) {
                int row = i / w4;
                int col = c0 + ((i - row * w4) << 2);
                int l = l0 - PAD + col;
                float4 v = make_float4(0.f, 0.f, 0.f, 0.f);
                if (l >= 0 && l < SEQLEN)
                    v = *(const float4*)&rin[(size_t)row * SEQLEN + l];
                *(float4*)&halo[row * HS + col] = v;
            }
        }
    }
    __syncthreads();

    int warp = tid >> 5;
    int lane = tid & 31;
    int n0 = warp * 16;
    int lcol = n0 + (lane & 15);
    int cbase = (lane >> 4) * 16;

    // ---------------- GEMM1: [f;g] = Wfg @ shifted residual ----------------
    wmma::fragment<wmma::accumulator, 16, 16, 8, float> acc[4];
#pragma unroll
    for (int mi = 0; mi < 4; mi++) wmma::fill_fragment(acc[mi], 0.f);

#pragma unroll
    for (int tap = 0; tap < 2; tap++) {
        const float* wAt = wA + tap * 64 * WALD;
        int tapOff = PAD + (tap ? offB : offA) + n0;
#pragma unroll
        for (int kf = 0; kf < 4; kf++) {
            wmma::fragment<wmma::matrix_a, 16, 16, 8, wmma::precision::tf32, wmma::row_major> a;
            wmma::fragment<wmma::matrix_b, 16, 16, 8, wmma::precision::tf32, wmma::row_major> bf;
            wmma::load_matrix_sync(bf, &halo[(kf * 8) * HS + tapOff], HS);
#pragma unroll
            for (int t = 0; t < bf.num_elements; t++)
                bf.x[t] = wmma::__float_to_tf32(bf.x[t]);
#pragma unroll
            for (int mi = 0; mi < 4; mi++) {
                wmma::load_matrix_sync(a, &wAt[(mi * 16) * WALD + kf * 8], WALD);
                wmma::mma_sync(acc[mi], a, bf, acc[mi]);
            }
        }
    }
#pragma unroll
    for (int mi = 0; mi < 4; mi++)
        wmma::store_matrix_sync(&u[(mi * 16) * FGLD + n0], acc[mi], FGLD, wmma::mem_row_major);
    __syncwarp();

    // ---------------- lo = tf32((f+bf)*(g+bg)) into u rows 0-31 ----------------
#pragma unroll
    for (int cc = 0; cc < 16; cc++) {
        int c = cbase + cc;
        float fv = u[c * FGLD + lcol] + bias[c];
        float gv = u[(32 + c) * FGLD + lcol] + bias[32 + c];
        u[c * FGLD + lcol] = wmma::__float_to_tf32(fv * gv);
    }
    __syncwarp();

    // ---------------- GEMM2: [res;skip] = Wrs @ lo ----------------
#pragma unroll
    for (int mi = 0; mi < 4; mi++) wmma::fill_fragment(acc[mi], 0.f);
    {
        const float* wA2 = wA + 2 * 64 * WALD;
#pragma unroll
        for (int kf = 0; kf < 4; kf++) {
            wmma::fragment<wmma::matrix_b, 16, 16, 8, wmma::precision::tf32, wmma::row_major> bf;
            wmma::load_matrix_sync(bf, &u[(kf * 8) * FGLD + n0], FGLD);
#pragma unroll
            for (int mi = 0; mi < 4; mi++) {
                wmma::fragment<wmma::matrix_a, 16, 16, 8, wmma::precision::tf32, wmma::row_major> a;
                wmma::load_matrix_sync(a, &wA2[(mi * 16) * WALD + kf * 8], WALD);
                wmma::mma_sync(acc[mi], a, bf, acc[mi]);
            }
        }
    }
#pragma unroll
    for (int mi = 0; mi < 4; mi++)
        wmma::store_matrix_sync(&u[(mi * 16) * FGLD + n0], acc[mi], FGLD, wmma::mem_row_major);
    __syncwarp();

    // ---------------- residual + skip epilogue (fp32, warp-local) ----------------
#pragma unroll
    for (int cc = 0; cc < 16; cc++) {
        int c = cbase + cc;
        size_t gidx = (size_t)c * SEQLEN + l0 + lcol;
        float rv = halo[c * HS + PAD + lcol] + u[c * FGLD + lcol] + bias[64 + c];
        float sv = u[(32 + c) * FGLD + lcol] + bias[96 + c];
        if (!firstLayer) sv += sk[gidx];
        rout[gidx] = rv;
        sk[gidx] = sv;
    }
}

// ----------------------------------------------------------------
// Fused head: hid = relu(W1e @ [relu(skip);1]); out = W2e @ [hid;1].
// CTA = 128 positions, 512 threads: 16 warps x 16 output rows for
// latency hiding (1 CTA/SM due to 160KB smem).
// ----------------------------------------------------------------
__global__ __launch_bounds__(512, 1)
void k_head(float* __restrict__ out)
{
    extern __shared__ float smem[];
    float* hid = smem;                  // [264][HLDH]
    float* bsk = smem + 264 * HLDH;     // [40][HLDH]

    int tid = threadIdx.x;
    int b = blockIdx.y;
    int l0 = blockIdx.x * HC;

    // B tile: tf32(relu(skip)) rows 0-31, row 32 = 1, rows 33-39 = 0
    for (int i = tid; i < 32 * 32; i += 512) {
        int row = i >> 5, n4 = (i & 31) << 2;
        float4 v = *(const float4*)&g_skip[((size_t)b * RC + row) * SEQLEN + l0 + n4];
        v.x = wmma::__float_to_tf32(v.x > 0.f ? v.x : 0.f);
        v.y = wmma::__float_to_tf32(v.y > 0.f ? v.y : 0.f);
        v.z = wmma::__float_to_tf32(v.z > 0.f ? v.z : 0.f);
        v.w = wmma::__float_to_tf32(v.w > 0.f ? v.w : 0.f);
        *(float4*)&bsk[row * HLDH + n4] = v;
    }
    for (int i = tid; i < 8 * HC; i += 512) {
        int row = 32 + (i >> 7), col = i & 127;
        bsk[row * HLDH + col] = (row == 32) ? 1.f : 0.f;
    }
    for (int i = tid; i < 8 * HC; i += 512) {
        int row = 256 + (i >> 7), col = i & 127;
        hid[row * HLDH + col] = (row == 256) ? 1.f : 0.f;
    }
    __syncthreads();

    int warp = tid >> 5;            // 0..15
    int m0 = warp * 16;             // this warp's 16 output rows
    wmma::fragment<wmma::accumulator, 16, 16, 8, float> acc[8];

    // ---------------- GEMM1 ----------------
#pragma unroll
    for (int ni = 0; ni < 8; ni++) wmma::fill_fragment(acc[ni], 0.f);

#pragma unroll
    for (int kf = 0; kf < 5; kf++) {
        wmma::fragment<wmma::matrix_a, 16, 16, 8, wmma::precision::tf32, wmma::row_major> a;
        wmma::load_matrix_sync(a, &g_w1e[m0 * 40 + kf * 8], 40);
#pragma unroll
        for (int ni = 0; ni < 8; ni++) {
            wmma::fragment<wmma::matrix_b, 16, 16, 8, wmma::precision::tf32, wmma::row_major> bf;
            wmma::load_matrix_sync(bf, &bsk[(kf * 8) * HLDH + ni * 16], HLDH);
            wmma::mma_sync(acc[ni], a, bf, acc[ni]);
        }
    }
#pragma unroll
    for (int ni = 0; ni < 8; ni++) {
#pragma unroll
        for (int t = 0; t < acc[ni].num_elements; t++) {
            float v = acc[ni].x[t];
            acc[ni].x[t] = wmma::__float_to_tf32(v > 0.f ? v : 0.f);
        }
        wmma::store_matrix_sync(&hid[m0 * HLDH + ni * 16], acc[ni], HLDH, wmma::mem_row_major);
    }
    __syncthreads();

    // ---------------- GEMM2: K = 264 ----------------
#pragma unroll
    for (int ni = 0; ni < 8; ni++) wmma::fill_fragment(acc[ni], 0.f);

    for (int kf = 0; kf < 33; kf++) {
        wmma::fragment<wmma::matrix_a, 16, 16, 8, wmma::precision::tf32, wmma::row_major> a;
        wmma::load_matrix_sync(a, &g_w2e[m0 * 264 + kf * 8], 264);
#pragma unroll
        for (int ni = 0; ni < 8; ni++) {
            wmma::fragment<wmma::matrix_b, 16, 16, 8, wmma::precision::tf32, wmma::row_major> bf;
            wmma::load_matrix_sync(bf, &hid[(kf * 8) * HLDH + ni * 16], HLDH);
            wmma::mma_sync(acc[ni], a, bf, acc[ni]);
        }
    }
#pragma unroll
    for (int ni = 0; ni < 8; ni++) {
        float* dst = &out[((size_t)b * OC + m0) * SEQLEN + l0 + ni * 16];
        wmma::store_matrix_sync(dst, acc[ni], SEQLEN, wmma::mem_row_major);
    }
}

// ----------------------------------------------------------------
extern "C" void kernel_launch(void* const* d_in, const int* in_sizes, int n_in,
                              void* d_out, int out_size)
{
    const float* x       = (const float*)d_in[0];
    const float* w_start = (const float*)d_in[1];
    const float* b_start = (const float*)d_in[2];
    const float* filt_w  = (const float*)d_in[3];
    const float* filt_b  = (const float*)d_in[4];
    const float* gate_w  = (const float*)d_in[5];
    const float* gate_b  = (const float*)d_in[6];
    const float* res_w   = (const float*)d_in[7];
    const float* res_b   = (const float*)d_in[8];
    const float* skip_w  = (const float*)d_in[9];
    const float* skip_b  = (const float*)d_in[10];
    const float* w_end1  = (const float*)d_in[11];
    const float* b_end1  = (const float*)d_in[12];
    const float* w_end2  = (const float*)d_in[13];
    const float* b_end2  = (const float*)d_in[14];
    float* out = (float*)d_out;

    static int smem_set = 0;
    if (!smem_set) {
        // max HS at PAD = offB = 256
        int tmp = 256 + TL + 256 + 4;
        int hsMax = ((tmp + 3) & ~7) + 4;
        cudaFuncSetAttribute(k_layer_tc, cudaFuncAttributeMaxDynamicSharedMemorySize,
                             (SM_FIXED + 32 * hsMax) * (int)sizeof(float));
        cudaFuncSetAttribute(k_head, cudaFuncAttributeMaxDynamicSharedMemorySize,
                             (264 * HLDH + 40 * HLDH) * (int)sizeof(float));
        smem_set = 1;
    }

    {
        int n = OC * 264 + OC * 40;
        k_prepw<<<(n + 255) / 256, 256>>>(w_end1, b_end1, w_end2, b_end2);
    }

    int ping = 0;
    dim3 gl(SEQLEN / TL, BATCH);
    for (int blk = 0; blk < NBLOCKS; blk++) {
        for (int i = 0; i < NLAYERS; i++) {
            int li = blk * NLAYERS + i;
            int offA, offB;
            if (i == 0) { offA = -1; offB = 0; }
            else { int h = 1 << (i - 1); offA = -h; offB = h; }
            int CO = -offA > offB ? -offA : offB;
            int PAD = (CO + 3) & ~3;
            int tmp = PAD + TL + offB + 4;
            int HS = ((tmp + 3) & ~7) + 4;          // >= tmp, ≡4 (mod 8)
            int smemBytes = (SM_FIXED + 32 * HS) * (int)sizeof(float);
            k_layer_tc<<<gl, 256, smemBytes>>>(ping,
                filt_w + (size_t)li * RC * RC * 2, filt_b + (size_t)li * RC,
                gate_w + (size_t)li * RC * RC * 2, gate_b + (size_t)li * RC,
                res_w  + (size_t)li * RC * RC,     res_b  + (size_t)li * RC,
                skip_w + (size_t)li * RC * RC,     skip_b + (size_t)li * RC,
                x, w_start, b_start,
                offA, offB, PAD, HS, (li == 0) ? 1 : 0);
            ping ^= 1;
        }
    }

    dim3 gh(SEQLEN / HC, BATCH);
    k_head<<<gh, 512, (264 * HLDH + 40 * HLDH) * sizeof(float)>>>(out);
}